// round 14
// baseline (speedup 1.0000x reference)
#include <cuda_runtime.h>
#include <cstdint>

#define B_   1024
#define F_   1024
#define E_   256
#define L1_  16
#define L2C_ 8
#define L3C_ 32
#define NE3_ 128

#define ROWS 16                   // rows per chunk
#define NSL  8                    // k-slices per chunk == cluster size
#define SL_K (F_ / NSL)           // 128

#define XPAD 9                    // ull stride per k-row (8 pairs + 1 pad)

#define MAXCHK2 80                // worst-case L2 chunk count (64 + 16)
#define MAXCHK  192               // worst-case L3 chunk count (64 + 128)

// Routing + schedule tables (static device memory; zero-initialized at load,
// re-zeroed by the last L3 block so graph replays start clean).
__device__ int g_cnt2[L1_];
__device__ int g_rows2[L1_ * B_];
__device__ int g_cnt3[NE3_];
__device__ int g_rows3[NE3_ * B_];
__device__ int g_t2_e[MAXCHK2], g_t2_off[MAXCHK2];
__device__ int g_t2_n;
__device__ int g_t3_e[MAXCHK], g_t3_off[MAXCHK];
__device__ int g_t3_n;
__device__ int g_done1, g_done2, g_done3;   // election counters (self-resetting)

// ---- packed f32x2 helpers (Blackwell FFMA2) ----
__device__ __forceinline__ unsigned long long pack2_dup(float a) {
    unsigned long long r;
    asm("mov.b64 %0, {%1, %1};" : "=l"(r) : "f"(a));
    return r;
}
__device__ __forceinline__ unsigned long long pack2(float a, float b) {
    unsigned long long r;
    asm("mov.b64 %0, {%1, %2};" : "=l"(r) : "f"(a), "f"(b));
    return r;
}
__device__ __forceinline__ void ffma2(unsigned long long& d,
                                      unsigned long long a, unsigned long long b) {
    asm("fma.rn.f32x2 %0, %1, %2, %0;" : "+l"(d) : "l"(a), "l"(b));
}

// ---- cluster / DSMEM helpers ----
#define CLUSTER_SYNC() do { \
    asm volatile("barrier.cluster.arrive.aligned;" ::: "memory"); \
    asm volatile("barrier.cluster.wait.aligned;" ::: "memory"); \
} while (0)

__device__ __forceinline__ uint32_t sptr(const void* p) {
    return (uint32_t)__cvta_generic_to_shared(p);
}
__device__ __forceinline__ float ld_dsmem(uint32_t laddr, int rank) {
    uint32_t ra; float v;
    asm("mapa.shared::cluster.u32 %0, %1, %2;" : "=r"(ra) : "r"(laddr), "r"(rank));
    asm volatile("ld.shared::cluster.f32 %0, [%1];" : "=f"(v) : "r"(ra));
    return v;
}

// ---------------- Fused level kernel -----------------------------------------
// Cluster = 8 blocks = the 8 k-slices of one 16-row chunk. Each block GEMMs its
// 128-k slice into its own smem; DSMEM-reduce gives block s rows {2s, 2s+1};
// each block finishes LN+ReLU+head+argmax for its 2 rows. No global partials.
template <int LEVEL, int LOUT, int TOTBLK>
__global__ __launch_bounds__(256, 4) __cluster_dims__(1, NSL, 1)
void k_level(
    const float* __restrict__ x, const float* __restrict__ y,
    const float* __restrict__ W1, const float* __restrict__ gma,
    const float* __restrict__ bta, const float* __restrict__ W2,
    const float* __restrict__ b2, float* __restrict__ out)
{
    __shared__ __align__(16) unsigned long long xs2[SL_K * XPAD];  // 9KB
    __shared__ __align__(16) float part[ROWS][E_];                 // 16KB
    __shared__ float hrow[2][E_];
    __shared__ float lrow[2][LOUT];
    __shared__ float redm[2], redr[2];
    __shared__ int rowids[ROWS];
    __shared__ int scn[NE3_ + 1];
    __shared__ int s_build;

    const int tid = threadIdx.x;
    const int b = blockIdx.x;     // chunk slot
    const int s = blockIdx.y;     // k-slice == cluster rank

    int e = 0, off = b * ROWS, cnt = B_;
    bool active = true;
    if (LEVEL != 1) {
        const int tn = (LEVEL == 2) ? g_t2_n : g_t3_n;
        if (b >= tn) {
            active = false;       // whole cluster inactive together
        } else {
            e   = (LEVEL == 2) ? g_t2_e[b]   : g_t3_e[b];
            off = (LEVEL == 2) ? g_t2_off[b] : g_t3_off[b];
            cnt = (LEVEL == 2) ? g_cnt2[e]   : g_cnt3[e];
        }
    }

    if (active) {
        if (tid < ROWS) {
            int rid = -1;
            int j = off + tid;
            if (j < cnt) {
                rid = (LEVEL == 1) ? j
                    : ((LEVEL == 2) ? g_rows2[e * B_ + j] : g_rows3[e * B_ + j]);
            }
            rowids[tid] = rid;
        }
        __syncthreads();

        // --- stage k-slice, packing row pairs: thread (rp = tid&7, f4 = tid>>3)
        {
            const int rp = tid & 7;
            const int f4 = tid >> 3;
            int r0 = rowids[2 * rp], r1 = rowids[2 * rp + 1];
            float4 a = make_float4(0.f, 0.f, 0.f, 0.f);
            float4 c = make_float4(0.f, 0.f, 0.f, 0.f);
            if (r0 >= 0) {
                a = reinterpret_cast<const float4*>(x)[r0 * (F_ / 4) + s * (SL_K / 4) + f4];
                if (LEVEL == 2) {
                    float4 yv = reinterpret_cast<const float4*>(y)[r0 * (F_ / 4) + s * (SL_K / 4) + f4];
                    a = make_float4(0.6f * a.x + 0.4f * yv.x, 0.6f * a.y + 0.4f * yv.y,
                                    0.6f * a.z + 0.4f * yv.z, 0.6f * a.w + 0.4f * yv.w);
                }
            }
            if (r1 >= 0) {
                c = reinterpret_cast<const float4*>(x)[r1 * (F_ / 4) + s * (SL_K / 4) + f4];
                if (LEVEL == 2) {
                    float4 yv = reinterpret_cast<const float4*>(y)[r1 * (F_ / 4) + s * (SL_K / 4) + f4];
                    c = make_float4(0.6f * c.x + 0.4f * yv.x, 0.6f * c.y + 0.4f * yv.y,
                                    0.6f * c.z + 0.4f * yv.z, 0.6f * c.w + 0.4f * yv.w);
                }
            }
            xs2[(4 * f4 + 0) * XPAD + rp] = pack2(a.x, c.x);
            xs2[(4 * f4 + 1) * XPAD + rp] = pack2(a.y, c.y);
            xs2[(4 * f4 + 2) * XPAD + rp] = pack2(a.z, c.z);
            xs2[(4 * f4 + 3) * XPAD + rp] = pack2(a.w, c.w);
        }
        __syncthreads();

        // --- GEMM: SL_K k x 16 rows for column `tid`, double-buffered weights
        unsigned long long acc2[8];
        #pragma unroll
        for (int m = 0; m < 8; ++m) acc2[m] = 0ULL;

        const float* Wp = W1 + ((size_t)e * F_ + (size_t)s * SL_K) * E_ + tid;

        float wc[8];
        #pragma unroll
        for (int j = 0; j < 8; ++j)
            wc[j] = Wp[(size_t)j * E_];

        #pragma unroll 1
        for (int kb = 0; kb < SL_K; kb += 8) {
            float wn[8];
            if (kb + 8 < SL_K) {   // prefetch next batch (8 independent LDG.32)
                #pragma unroll
                for (int j = 0; j < 8; ++j)
                    wn[j] = Wp[(size_t)(kb + 8 + j) * E_];
            }
            #pragma unroll
            for (int j = 0; j < 8; ++j) {
                unsigned long long wd = pack2_dup(wc[j]);
                const ulonglong2* xk =
                    reinterpret_cast<const ulonglong2*>(&xs2[(kb + j) * XPAD]);
                #pragma unroll
                for (int i = 0; i < 4; ++i) {
                    ulonglong2 u = xk[i];
                    ffma2(acc2[2 * i],     u.x, wd);
                    ffma2(acc2[2 * i + 1], u.y, wd);
                }
            }
            if (kb + 8 < SL_K) {
                #pragma unroll
                for (int j = 0; j < 8; ++j)
                    wc[j] = wn[j];
            }
        }

        // partials -> own smem (no global traffic)
        #pragma unroll
        for (int m = 0; m < 8; ++m) {
            float lo, hi;
            asm("mov.b64 {%0, %1}, %2;" : "=f"(lo), "=f"(hi) : "l"(acc2[m]));
            part[2 * m][tid]     = lo;
            part[2 * m + 1][tid] = hi;
        }

        // --- cluster reduce: block s owns rows {2s, 2s+1} ---------------------
        CLUSTER_SYNC();
        float r0sum = 0.f, r1sum = 0.f;
        {
            uint32_t l0 = sptr(&part[2 * s][tid]);
            uint32_t l1 = sptr(&part[2 * s + 1][tid]);
            #pragma unroll
            for (int k = 0; k < NSL; ++k) {      // fixed rank order: deterministic
                r0sum += ld_dsmem(l0, k);
                r1sum += ld_dsmem(l1, k);
            }
        }
        CLUSTER_SYNC();           // all remote reads done before any CTA moves on

        hrow[0][tid] = r0sum;
        hrow[1][tid] = r1sum;
        __syncthreads();

        // LayerNorm stats: warps 0,1 reduce rows 0,1
        {
            int w = tid >> 5, lane = tid & 31;
            if (w < 2) {
                float sv = 0.f, ss = 0.f;
                #pragma unroll
                for (int k = lane; k < E_; k += 32) {
                    float v = hrow[w][k];
                    sv += v; ss += v * v;
                }
                #pragma unroll
                for (int o = 16; o > 0; o >>= 1) {
                    sv += __shfl_xor_sync(0xffffffffu, sv, o);
                    ss += __shfl_xor_sync(0xffffffffu, ss, o);
                }
                if (lane == 0) {
                    float m = sv * (1.f / E_);
                    float var = ss * (1.f / E_) - m * m;
                    redm[w] = m;
                    redr[w] = rsqrtf(var + 1e-5f);
                }
            }
        }
        __syncthreads();

        // normalize + affine + ReLU
        {
            float gv = gma[e * E_ + tid], bv = bta[e * E_ + tid];
            #pragma unroll
            for (int r = 0; r < 2; ++r) {
                float v = (hrow[r][tid] - redm[r]) * redr[r] * gv + bv;
                hrow[r][tid] = fmaxf(v, 0.f);
            }
        }
        __syncthreads();

        // head GEMM: tasks (r in {0,1}, cc), ILP-4; W2 via L2 (hot: broadcast)
        const float* W2_e = W2 + (size_t)e * E_ * LOUT;
        const int outoff = (LEVEL == 1) ? 0
                         : ((LEVEL == 2) ? B_ * L1_ : B_ * (L1_ + L2C_));
        if (tid < 2 * LOUT) {
            int r = tid / LOUT, cc = tid % LOUT;
            int row = rowids[2 * s + r];
            if (row >= 0) {
                float s0 = b2[e * LOUT + cc], s1 = 0.f, s2 = 0.f, s3 = 0.f;
                #pragma unroll
                for (int k = 0; k < E_; k += 4) {
                    float4 h4 = *reinterpret_cast<const float4*>(&hrow[r][k]);
                    s0 = fmaf(h4.x, __ldg(&W2_e[(k + 0) * LOUT + cc]), s0);
                    s1 = fmaf(h4.y, __ldg(&W2_e[(k + 1) * LOUT + cc]), s1);
                    s2 = fmaf(h4.z, __ldg(&W2_e[(k + 2) * LOUT + cc]), s2);
                    s3 = fmaf(h4.w, __ldg(&W2_e[(k + 3) * LOUT + cc]), s3);
                }
                float sv = (s0 + s1) + (s2 + s3);
                out[outoff + row * LOUT + cc] = sv;
                if (LEVEL != 3) lrow[r][cc] = sv;
            }
        }

        // argmax + bucket push (levels 1, 2); first-max semantics
        if (LEVEL != 3) {
            __syncthreads();
            if (tid < 2) {
                int row = rowids[2 * s + tid];
                if (row >= 0) {
                    float best = lrow[tid][0];
                    int bi = 0;
                    #pragma unroll
                    for (int cc = 1; cc < LOUT; ++cc) {
                        float v = lrow[tid][cc];
                        if (v > best) { best = v; bi = cc; }
                    }
                    if (LEVEL == 1) {
                        int pos = atomicAdd(&g_cnt2[bi], 1);
                        g_rows2[bi * B_ + pos] = row;
                    } else {
                        int ei = e * L2C_ + bi;
                        int pos = atomicAdd(&g_cnt3[ei], 1);
                        g_rows3[ei * B_ + pos] = row;
                    }
                }
            }
        }
    }

    // --- last-block election: build next table (L1,L2) or cleanup (L3) -------
    __threadfence();
    __syncthreads();
    if (tid == 0) {
        int* dn = (LEVEL == 1) ? &g_done1 : ((LEVEL == 2) ? &g_done2 : &g_done3);
        s_build = (atomicAdd(dn, 1) == TOTBLK - 1) ? 1 : 0;
    }
    __syncthreads();
    if (s_build) {
        __threadfence();
        if (LEVEL != 3) {
            const int NE = (LEVEL == 1) ? L1_ : NE3_;
            const int* cn = (LEVEL == 1) ? g_cnt2 : g_cnt3;
            int* te = (LEVEL == 1) ? g_t2_e   : g_t3_e;
            int* to = (LEVEL == 1) ? g_t2_off : g_t3_off;
            if (tid < NE) scn[tid + 1] = (cn[tid] + ROWS - 1) / ROWS;
            if (tid == 0) scn[0] = 0;
            __syncthreads();
            if (tid == 0) {
                int a = 0;
                #pragma unroll 1
                for (int i = 1; i <= NE; ++i) { a += scn[i]; scn[i] = a; }
                if (LEVEL == 1) { g_t2_n = a; g_done1 = 0; }
                else            { g_t3_n = a; g_done2 = 0; }
            }
            __syncthreads();
            if (tid < NE) {
                int st = scn[tid], en = scn[tid + 1];
                for (int i = st; i < en; ++i) {
                    te[i] = tid;
                    to[i] = (i - st) * ROWS;
                }
            }
        } else {
            // cleanup for next graph replay
            if (tid < L1_)  g_cnt2[tid] = 0;
            if (tid < NE3_) g_cnt3[tid] = 0;
            if (tid == 0)   g_done3 = 0;
        }
    }
}

extern "C" void kernel_launch(void* const* d_in, const int* in_sizes, int n_in,
                              void* d_out, int out_size) {
    const float* x    = (const float*)d_in[0];
    const float* y    = (const float*)d_in[1];
    const float* l1W1 = (const float*)d_in[2];
    const float* l1g  = (const float*)d_in[3];
    const float* l1b  = (const float*)d_in[4];
    const float* l1W2 = (const float*)d_in[5];
    const float* l1b2 = (const float*)d_in[6];
    const float* l2W1 = (const float*)d_in[7];
    const float* l2g  = (const float*)d_in[8];
    const float* l2b  = (const float*)d_in[9];
    const float* l2W2 = (const float*)d_in[10];
    const float* l2b2 = (const float*)d_in[11];
    const float* l3W1 = (const float*)d_in[12];
    const float* l3g  = (const float*)d_in[13];
    const float* l3b  = (const float*)d_in[14];
    const float* l3W2 = (const float*)d_in[15];
    const float* l3b2 = (const float*)d_in[16];
    float* out = (float*)d_out;

    // Level 1: dense, 64 chunks x 8 slices (clusters of 8).
    k_level<1, L1_, 64 * NSL><<<dim3(64, NSL), 256>>>(
        x, y, l1W1, l1g, l1b, l1W2, l1b2, out);

    // Level 2: <= 80 chunks (table built by last L1 block).
    k_level<2, L2C_, MAXCHK2 * NSL><<<dim3(MAXCHK2, NSL), 256>>>(
        x, y, l2W1, l2g, l2b, l2W2, l2b2, out);

    // Level 3: <= 192 chunks (table built by last L2 block; cleans up after).
    k_level<3, L3C_, MAXCHK * NSL><<<dim3(MAXCHK, NSL), 256>>>(
        x, y, l3W1, l3g, l3b, l3W2, l3b2, out);
}

// round 16
// speedup vs baseline: 1.1159x; 1.1159x over previous
#include <cuda_runtime.h>
#include <cstdint>

#define B_   1024
#define F_   1024
#define E_   256
#define L1_  16
#define L2C_ 8
#define L3C_ 32
#define NE3_ 128

#define ROWS 16                   // rows per chunk (GEMM)
#define ERW  4                    // rows per epilogue block
#define NSL  8                    // k-slices per chunk
#define SL_K (F_ / NSL)           // 128

#define XPAD 9                    // ull stride per k-row (8 pairs + 1 pad)

#define MAXCHK2 80                // worst-case L2 chunk count (64 + 16)
#define MAXCHK  192               // worst-case L3 chunk count (64 + 128)

// Routing + schedule tables + partial scratch (static device memory).
__device__ int g_cnt2[L1_];
__device__ int g_rows2[L1_ * B_];
__device__ int g_cnt3[NE3_];
__device__ int g_rows3[NE3_ * B_];
__device__ int g_t2_e[MAXCHK2], g_t2_off[MAXCHK2];
__device__ int g_t2_n;
__device__ int g_t3_e[MAXCHK], g_t3_off[MAXCHK];
__device__ int g_t3_n;
__device__ int g_done1, g_done2;      // epi completion counters (self-resetting)
// partials: [chunk][slice][row ROWS][col E_]
__device__ float g_part[MAXCHK * NSL * ROWS * E_];

// ---- packed f32x2 helpers (Blackwell FFMA2) ----
__device__ __forceinline__ unsigned long long pack2_dup(float a) {
    unsigned long long r;
    asm("mov.b64 %0, {%1, %1};" : "=l"(r) : "f"(a));
    return r;
}
__device__ __forceinline__ unsigned long long pack2(float a, float b) {
    unsigned long long r;
    asm("mov.b64 %0, {%1, %2};" : "=l"(r) : "f"(a), "f"(b));
    return r;
}
__device__ __forceinline__ void ffma2(unsigned long long& d,
                                      unsigned long long a, unsigned long long b) {
    asm("fma.rn.f32x2 %0, %1, %2, %0;" : "+l"(d) : "l"(a), "l"(b));
}

// ---- L2 cache-policy helpers (createpolicy + cache_hint form) ----
__device__ __forceinline__ unsigned long long pol_evict_first() {
    unsigned long long p;
    asm("createpolicy.fractional.L2::evict_first.b64 %0, 1.0;" : "=l"(p));
    return p;
}
__device__ __forceinline__ unsigned long long pol_evict_last() {
    unsigned long long p;
    asm("createpolicy.fractional.L2::evict_last.b64 %0, 1.0;" : "=l"(p));
    return p;
}
// Weight stream: read-once, evict-first.
__device__ __forceinline__ float ldg_stream(const float* p, unsigned long long pol) {
    float v;
    asm volatile("ld.global.nc.L2::cache_hint.f32 %0, [%1], %2;"
                 : "=f"(v) : "l"(p), "l"(pol));
    return v;
}
// Partials: pin in L2 until consumed.
__device__ __forceinline__ void stg_keep(float* p, float v, unsigned long long pol) {
    asm volatile("st.global.L2::cache_hint.f32 [%0], %1, %2;"
                 :: "l"(p), "f"(v), "l"(pol));
}
// Partial consume: dead after first read.
__device__ __forceinline__ float ldg_once(const float* p, unsigned long long pol) {
    float v;
    asm volatile("ld.global.L2::cache_hint.f32 %0, [%1], %2;"
                 : "=f"(v) : "l"(p), "l"(pol));
    return v;
}

// ---------------- GEMM pass: block = (chunk slot, k-slice) ------------------
// 256 threads; thread owns output column `tid`; 16 rows (8 packed pairs); SL_K k.
template <int LEVEL>
__global__ void __launch_bounds__(256, 4) k_gemm(
    const float* __restrict__ x, const float* __restrict__ y,
    const float* __restrict__ W1)
{
    // xs2[k][rp]: packed pair {row 2rp, row 2rp+1} at depth k.
    __shared__ __align__(16) unsigned long long xs2[SL_K * XPAD];
    __shared__ int rowids[ROWS];

    const int tid = threadIdx.x;
    const int b = blockIdx.x;     // chunk slot
    const int s = blockIdx.y;     // k-slice

    // fold count-zeroing into the first L1 GEMM block (saves a launch);
    // safe: counts are untouched until the L1 epilogue kernel.
    if (LEVEL == 1 && b == 0 && s == 0) {
        if (tid < L1_)  g_cnt2[tid] = 0;
        if (tid < NE3_) g_cnt3[tid] = 0;
    }

    int e = 0, off = b * ROWS, cnt = B_;
    if (LEVEL != 1) {
        const int tn = (LEVEL == 2) ? g_t2_n : g_t3_n;
        if (b >= tn) return;
        e   = (LEVEL == 2) ? g_t2_e[b]   : g_t3_e[b];
        off = (LEVEL == 2) ? g_t2_off[b] : g_t3_off[b];
        cnt = (LEVEL == 2) ? g_cnt2[e]   : g_cnt3[e];
    }

    if (tid < ROWS) {
        int rid = -1;
        int j = off + tid;
        if (j < cnt) {
            rid = (LEVEL == 1) ? j
                : ((LEVEL == 2) ? g_rows2[e * B_ + j] : g_rows3[e * B_ + j]);
        }
        rowids[tid] = rid;
    }
    __syncthreads();

    // --- stage k-slice, packing row pairs: thread (rp = tid&7, f4 = tid>>3) ---
    {
        const int rp = tid & 7;
        const int f4 = tid >> 3;
        int r0 = rowids[2 * rp], r1 = rowids[2 * rp + 1];
        float4 a = make_float4(0.f, 0.f, 0.f, 0.f);
        float4 c = make_float4(0.f, 0.f, 0.f, 0.f);
        if (r0 >= 0) {
            a = reinterpret_cast<const float4*>(x)[r0 * (F_ / 4) + s * (SL_K / 4) + f4];
            if (LEVEL == 2) {
                float4 yv = reinterpret_cast<const float4*>(y)[r0 * (F_ / 4) + s * (SL_K / 4) + f4];
                a = make_float4(0.6f * a.x + 0.4f * yv.x, 0.6f * a.y + 0.4f * yv.y,
                                0.6f * a.z + 0.4f * yv.z, 0.6f * a.w + 0.4f * yv.w);
            }
        }
        if (r1 >= 0) {
            c = reinterpret_cast<const float4*>(x)[r1 * (F_ / 4) + s * (SL_K / 4) + f4];
            if (LEVEL == 2) {
                float4 yv = reinterpret_cast<const float4*>(y)[r1 * (F_ / 4) + s * (SL_K / 4) + f4];
                c = make_float4(0.6f * c.x + 0.4f * yv.x, 0.6f * c.y + 0.4f * yv.y,
                                0.6f * c.z + 0.4f * yv.z, 0.6f * c.w + 0.4f * yv.w);
            }
        }
        xs2[(4 * f4 + 0) * XPAD + rp] = pack2(a.x, c.x);
        xs2[(4 * f4 + 1) * XPAD + rp] = pack2(a.y, c.y);
        xs2[(4 * f4 + 2) * XPAD + rp] = pack2(a.z, c.z);
        xs2[(4 * f4 + 3) * XPAD + rp] = pack2(a.w, c.w);
    }
    __syncthreads();

    // --- GEMM: SL_K k x 16 rows for column `tid`, double-buffered weights ---
    unsigned long long acc2[8];
    #pragma unroll
    for (int m = 0; m < 8; ++m) acc2[m] = 0ULL;

    const unsigned long long pf = pol_evict_first();
    const float* Wp = W1 + ((size_t)e * F_ + (size_t)s * SL_K) * E_ + tid;

    float wc[8];
    #pragma unroll
    for (int j = 0; j < 8; ++j)
        wc[j] = ldg_stream(Wp + (size_t)j * E_, pf);

    #pragma unroll 1
    for (int kb = 0; kb < SL_K; kb += 8) {
        float wn[8];
        if (kb + 8 < SL_K) {       // prefetch next batch (8 independent LDG.32)
            #pragma unroll
            for (int j = 0; j < 8; ++j)
                wn[j] = ldg_stream(Wp + (size_t)(kb + 8 + j) * E_, pf);
        }
        #pragma unroll
        for (int j = 0; j < 8; ++j) {
            unsigned long long wd = pack2_dup(wc[j]);
            const ulonglong2* xk =
                reinterpret_cast<const ulonglong2*>(&xs2[(kb + j) * XPAD]);
            #pragma unroll
            for (int i = 0; i < 4; ++i) {
                ulonglong2 u = xk[i];
                ffma2(acc2[2 * i],     u.x, wd);
                ffma2(acc2[2 * i + 1], u.y, wd);
            }
        }
        if (kb + 8 < SL_K) {
            #pragma unroll
            for (int j = 0; j < 8; ++j)
                wc[j] = wn[j];
        }
    }

    // write partials (coalesced, pinned in L2): acc2[m] = rows {2m, 2m+1}
    const unsigned long long pl = pol_evict_last();
    float* dst = g_part + ((size_t)(b * NSL + s) * ROWS) * E_ + tid;
    #pragma unroll
    for (int m = 0; m < 8; ++m) {
        float lo, hi;
        asm("mov.b64 {%0, %1}, %2;" : "=f"(lo), "=f"(hi) : "l"(acc2[m]));
        stg_keep(&dst[(2 * m) * E_],     lo, pl);
        stg_keep(&dst[(2 * m + 1) * E_], hi, pl);
    }
}

// ---------------- Epilogue pass: block = (chunk slot, 4-row group) ----------
// Reduce NSL slice-partials (4 rows), LN+ReLU, ILP-4 head GEMM, argmax+push.
// The LAST finishing block (levels 1,2) builds the next level's chunk table.
template <int LEVEL, int LOUT, int TOTBLK>
__global__ void __launch_bounds__(256) k_epi(
    const float* __restrict__ gma, const float* __restrict__ bta,
    const float* __restrict__ W2, const float* __restrict__ b2,
    float* __restrict__ out)
{
    __shared__ float ht[ERW][E_];        // 4KB
    __shared__ float w2s[E_ * LOUT];     // <= 32KB
    __shared__ float lrow[ERW][LOUT];
    __shared__ float redm[ERW], redr[ERW];
    __shared__ int rowids[ERW];
    __shared__ int scn[NE3_ + 1];
    __shared__ int s_build;

    const int tid = threadIdx.x;
    const int b = blockIdx.x;            // chunk slot
    const int g = blockIdx.y;            // 4-row group within 16-row chunk

    int e = 0, off = b * ROWS, cnt = B_;
    bool active = true;
    if (LEVEL != 1) {
        const int tn = (LEVEL == 2) ? g_t2_n : g_t3_n;
        if (b >= tn) {
            active = false;
        } else {
            e   = (LEVEL == 2) ? g_t2_e[b]   : g_t3_e[b];
            off = (LEVEL == 2) ? g_t2_off[b] : g_t3_off[b];
            cnt = (LEVEL == 2) ? g_cnt2[e]   : g_cnt3[e];
        }
    }
    if (active && off + g * ERW >= cnt) active = false;

    if (active) {
        const float* W2_e = W2 + (size_t)e * E_ * LOUT;
        const int outoff = (LEVEL == 1) ? 0
                         : ((LEVEL == 2) ? B_ * L1_ : B_ * (L1_ + L2C_));

        // reduce partials FIRST (longest-latency loads; all independent):
        // thread owns column tid, ERW rows x NSL slices = 32 loads in flight.
        {
            const unsigned long long pf = pol_evict_first();
            const float* base = g_part + (size_t)b * NSL * ROWS * E_
                              + (g * ERW) * E_ + tid;
            float sacc[ERW];
            #pragma unroll
            for (int r = 0; r < ERW; ++r) sacc[r] = 0.f;
            #pragma unroll
            for (int sl = 0; sl < NSL; ++sl) {
                #pragma unroll
                for (int r = 0; r < ERW; ++r)
                    sacc[r] += ldg_once(&base[(sl * ROWS + r) * E_], pf);
            }
            #pragma unroll
            for (int r = 0; r < ERW; ++r)
                ht[r][tid] = sacc[r];
        }
        // stage W2 (independent; overlaps partial loads)
        for (int i = tid * 4; i < E_ * LOUT; i += 1024)
            *reinterpret_cast<float4*>(&w2s[i]) =
                *reinterpret_cast<const float4*>(&W2_e[i]);
        if (tid < ERW) {
            int rid = -1;
            int j = off + g * ERW + tid;
            if (j < cnt) {
                rid = (LEVEL == 1) ? j
                    : ((LEVEL == 2) ? g_rows2[e * B_ + j] : g_rows3[e * B_ + j]);
            }
            rowids[tid] = rid;
        }
        __syncthreads();

        // LayerNorm stats: warp w (< ERW) reduces row w
        {
            int w = tid >> 5, lane = tid & 31;
            if (w < ERW) {
                float sv = 0.f, ss = 0.f;
                #pragma unroll
                for (int k = lane; k < E_; k += 32) {
                    float v = ht[w][k];
                    sv += v; ss += v * v;
                }
                #pragma unroll
                for (int o = 16; o > 0; o >>= 1) {
                    sv += __shfl_xor_sync(0xffffffffu, sv, o);
                    ss += __shfl_xor_sync(0xffffffffu, ss, o);
                }
                if (lane == 0) {
                    float m = sv * (1.f / E_);
                    float var = ss * (1.f / E_) - m * m;
                    redm[w] = m;
                    redr[w] = rsqrtf(var + 1e-5f);
                }
            }
        }
        __syncthreads();

        // normalize + affine + ReLU
        {
            float gv = gma[e * E_ + tid], bv = bta[e * E_ + tid];
            #pragma unroll
            for (int r = 0; r < ERW; ++r) {
                float v = (ht[r][tid] - redm[r]) * redr[r] * gv + bv;
                ht[r][tid] = fmaxf(v, 0.f);
            }
        }
        __syncthreads();

        // head GEMM: task (r, cc), ILP-4 accumulators, <= 128 tasks
        if (tid < ERW * LOUT) {
            int r = tid / LOUT, cc = tid % LOUT;
            int row = rowids[r];
            if (row >= 0) {
                float s0 = b2[e * LOUT + cc], s1 = 0.f, s2 = 0.f, s3 = 0.f;
                #pragma unroll
                for (int k = 0; k < E_; k += 4) {
                    float4 h4 = *reinterpret_cast<const float4*>(&ht[r][k]);
                    s0 = fmaf(h4.x, w2s[(k + 0) * LOUT + cc], s0);
                    s1 = fmaf(h4.y, w2s[(k + 1) * LOUT + cc], s1);
                    s2 = fmaf(h4.z, w2s[(k + 2) * LOUT + cc], s2);
                    s3 = fmaf(h4.w, w2s[(k + 3) * LOUT + cc], s3);
                }
                float sv = (s0 + s1) + (s2 + s3);
                out[outoff + row * LOUT + cc] = sv;
                if (LEVEL != 3) lrow[r][cc] = sv;
            }
        }

        // argmax + bucket push (levels 1, 2); first-max semantics
        if (LEVEL != 3) {
            __syncthreads();
            if (tid < ERW) {
                int row = rowids[tid];
                if (row >= 0) {
                    float best = lrow[tid][0];
                    int bi = 0;
                    #pragma unroll
                    for (int cc = 1; cc < LOUT; ++cc) {
                        float v = lrow[tid][cc];
                        if (v > best) { best = v; bi = cc; }
                    }
                    if (LEVEL == 1) {
                        int pos = atomicAdd(&g_cnt2[bi], 1);
                        g_rows2[bi * B_ + pos] = row;
                    } else {
                        int ei = e * L2C_ + bi;
                        int pos = atomicAdd(&g_cnt3[ei], 1);
                        g_rows3[ei * B_ + pos] = row;
                    }
                }
            }
        }
    }

    // --- last-block election: build next level's chunk table -----------------
    if (LEVEL != 3) {
        __threadfence();
        __syncthreads();
        if (tid == 0) {
            int* dn = (LEVEL == 1) ? &g_done1 : &g_done2;
            s_build = (atomicAdd(dn, 1) == TOTBLK - 1) ? 1 : 0;
        }
        __syncthreads();
        if (s_build) {
            __threadfence();
            const int NE = (LEVEL == 1) ? L1_ : NE3_;
            const int* cn = (LEVEL == 1) ? g_cnt2 : g_cnt3;
            int* te = (LEVEL == 1) ? g_t2_e   : g_t3_e;
            int* to = (LEVEL == 1) ? g_t2_off : g_t3_off;
            if (tid < NE) scn[tid + 1] = (cn[tid] + ROWS - 1) / ROWS;
            if (tid == 0) scn[0] = 0;
            __syncthreads();
            if (tid == 0) {
                int a = 0;
                #pragma unroll 1
                for (int i = 1; i <= NE; ++i) { a += scn[i]; scn[i] = a; }
                if (LEVEL == 1) { g_t2_n = a; g_done1 = 0; }
                else            { g_t3_n = a; g_done2 = 0; }
            }
            __syncthreads();
            if (tid < NE) {
                int st = scn[tid], en = scn[tid + 1];
                for (int i = st; i < en; ++i) {
                    te[i] = tid;
                    to[i] = (i - st) * ROWS;
                }
            }
        }
    }
}

extern "C" void kernel_launch(void* const* d_in, const int* in_sizes, int n_in,
                              void* d_out, int out_size) {
    const float* x    = (const float*)d_in[0];
    const float* y    = (const float*)d_in[1];
    const float* l1W1 = (const float*)d_in[2];
    const float* l1g  = (const float*)d_in[3];
    const float* l1b  = (const float*)d_in[4];
    const float* l1W2 = (const float*)d_in[5];
    const float* l1b2 = (const float*)d_in[6];
    const float* l2W1 = (const float*)d_in[7];
    const float* l2g  = (const float*)d_in[8];
    const float* l2b  = (const float*)d_in[9];
    const float* l2W2 = (const float*)d_in[10];
    const float* l2b2 = (const float*)d_in[11];
    const float* l3W1 = (const float*)d_in[12];
    const float* l3g  = (const float*)d_in[13];
    const float* l3b  = (const float*)d_in[14];
    const float* l3W2 = (const float*)d_in[15];
    const float* l3b2 = (const float*)d_in[16];
    float* out = (float*)d_out;

    // Level 1: dense, 64 chunks x 8 k-slices (counts zeroed by block (0,0)).
    k_gemm<1><<<dim3(64, NSL), 256>>>(x, y, l1W1);
    k_epi <1, L1_, 64 * 4><<<dim3(64, 4), 256>>>(l1g, l1b, l1W2, l1b2, out);

    // Level 2: <= 80 chunks (table built by last L1 epi block).
    k_gemm<2><<<dim3(MAXCHK2, NSL), 256>>>(x, y, l2W1);
    k_epi <2, L2C_, MAXCHK2 * 4><<<dim3(MAXCHK2, 4), 256>>>(l2g, l2b, l2W2, l2b2, out);

    // Level 3: <= 192 chunks (table built by last L2 epi block).
    k_gemm<3><<<dim3(MAXCHK, NSL), 256>>>(x, y, l3W1);
    k_epi <3, L3C_, 0><<<dim3(MAXCHK, 4), 256>>>(l3g, l3b, l3W2, l3b2, out);
}